// round 8
// baseline (speedup 1.0000x reference)
#include <cuda_runtime.h>
#include <cuda_bf16.h>
#include <cstdint>

#define B       128
#define T       256
#define H       1024
#define NG      4096
#define THREADS 512
#define CTAS    128
#define JPC     8
#define NCHUNK  16          // 16 chunks of k=64
#define NBUF    3

// ---- persistent device state ----
// h in mma-A-fragment layout: [buf][chunk*1024 + qs*256 + m*32 + lane] (uint4)
__device__ uint4 g_hfH[NBUF][NCHUNK * 1024];
__device__ uint4 g_hfL[NBUF][NCHUNK * 1024];
__device__ int  g_flag[NCHUNK];              // 64 increments per chunk per step
__device__ unsigned int g_bar_arrive = 0;
__device__ volatile unsigned int g_bar_gen = 0;

// ---- SMEM layout (bytes) ----
#define U_RSTRIDE 2064      // U^T rows padded -> conflict-free ldmatrix
#define OFF_UHI 0           // 66048
#define OFF_ULO 66048       // 66048
#define OFF_ZX  132096      // 2 x 16384  z exchange (double-buffered by step parity)
#define OFF_W   164864      // 4*32 f32
#define OFF_BS  165376      // 32 f32
#define SMEM_TOTAL 165504

__device__ __forceinline__ uint32_t smem_u32(const void* p) {
    uint32_t a;
    asm("{ .reg .u64 t; cvta.to.shared.u64 t, %1; cvt.u32.u64 %0, t; }"
        : "=r"(a) : "l"(p));
    return a;
}

#define LDSM_X4(r0, r1, r2, r3, a) \
    asm volatile("ldmatrix.sync.aligned.m8n8.x4.shared.b16 {%0,%1,%2,%3}, [%4];" \
                 : "=r"(r0), "=r"(r1), "=r"(r2), "=r"(r3) : "r"(a))

#define MMA_BF16(d, a0, a1, a2, a3, b0, b1) \
    asm volatile("mma.sync.aligned.m16n8k16.row.col.f32.bf16.bf16.f32 " \
                 "{%0,%1,%2,%3}, {%4,%5,%6,%7}, {%8,%9}, {%0,%1,%2,%3};" \
                 : "+f"((d)[0]), "+f"((d)[1]), "+f"((d)[2]), "+f"((d)[3]) \
                 : "r"(a0), "r"(a1), "r"(a2), "r"(a3), "r"(b0), "r"(b1))

__device__ __forceinline__ void grid_barrier() {
    __syncthreads();
    __threadfence();
    if (threadIdx.x == 0) {
        unsigned int gen = g_bar_gen;
        if (atomicAdd(&g_bar_arrive, 1u) == CTAS - 1) {
            g_bar_arrive = 0;
            __threadfence();
            g_bar_gen = gen + 1;
        } else {
            while (g_bar_gen == gen) { }
        }
    }
    __syncthreads();
}

// acquire-spin until chunk flag reaches target
__device__ __forceinline__ void wait_flag(const int* f, int target) {
    int v;
    for (;;) {
        asm volatile("ld.acquire.gpu.global.b32 %0, [%1];"
                     : "=r"(v) : "l"(f) : "memory");
        if (v >= target) break;
    }
}

__device__ __forceinline__ uint32_t packbf(__nv_bfloat16 a, __nv_bfloat16 b) {
    return (uint32_t)__bfloat16_as_ushort(a) | ((uint32_t)__bfloat16_as_ushort(b) << 16);
}

// load this warp's 2 A-fragment pairs (q=0,1) for chunk c from L2 into regs
__device__ __forceinline__ void ldfrags(uint4* rh, uint4* rl,
                                        const uint4* __restrict__ HH,
                                        const uint4* __restrict__ HL,
                                        int c, int kh2, int m, int lid) {
#pragma unroll
    for (int q = 0; q < 2; ++q) {
        const int idx = c * 1024 + (kh2 + q) * 256 + m * 32 + lid;
        rh[q] = __ldcg(HH + idx);
        rl[q] = __ldcg(HL + idx);
    }
}

__global__ void __launch_bounds__(THREADS, 1)
lstm_frag_kernel(const float* __restrict__ seq,
                 const float* __restrict__ W,
                 const float* __restrict__ U,
                 const float* __restrict__ bias,
                 float* __restrict__ out,
                 int write_extras)
{
    extern __shared__ __align__(1024) uint8_t smem[];
    const uint32_t sbase = smem_u32(smem);
    const int tid = threadIdx.x;
    const int wid = tid >> 5;
    const int lid = tid & 31;
    const int m   = wid & 7;          // m-tile 0..7 (16 batch rows each)
    const int kh  = wid >> 3;         // k-half of each chunk
    const int cta = blockIdx.x;
    const int j0  = cta * JPC;
    const int Kc  = cta >> 1;         // frag kstep this CTA's j-columns land in
    const int codd = cta & 1;
    const int mychunk = Kc >> 2;      // chunk this CTA's h-slice lives in

    float*  Wsl  = (float*)(smem + OFF_W);
    float*  bsl  = (float*)(smem + OFF_BS);

    // ---------------- prologue ----------------
    // U slice -> U^T bf16 hi/lo (row n = gate*8+jj, k contiguous)
    for (int idx = tid; idx < 32 * H; idx += THREADS) {
        int k = idx >> 5, n = idx & 31;
        int gcol = ((n >> 3) << 10) + j0 + (n & 7);
        float v = U[(size_t)k * NG + gcol];
        __nv_bfloat16 hi = __float2bfloat16(v);
        __nv_bfloat16 lo = __float2bfloat16(v - __bfloat162float(hi));
        *(__nv_bfloat16*)(smem + OFF_UHI + n * U_RSTRIDE + k * 2) = hi;
        *(__nv_bfloat16*)(smem + OFF_ULO + n * U_RSTRIDE + k * 2) = lo;
    }
    if (tid < 4 * 32) {
        int f = tid >> 5, cc = tid & 31;
        Wsl[tid] = W[f * NG + ((cc >> 3) << 10) + j0 + (cc & 7)];
    }
    if (tid < 32)
        bsl[tid] = bias[((tid >> 3) << 10) + j0 + (tid & 7)];
    // zero-init this CTA's h-frag region in buf 0 (its 8B half of each elem)
    if (tid < 256) {
        int mm = tid >> 5, lane = tid & 31;
        int gidx = mychunk * 1024 + (Kc & 3) * 256 + mm * 32 + lane;
        ((uint2*)&g_hfH[0][gidx])[codd] = make_uint2(0u, 0u);
        ((uint2*)&g_hfL[0][gidx])[codd] = make_uint2(0u, 0u);
    }
    // reset dataflow flags (graph replays must start from 0)
    if (tid == 0 && cta < NCHUNK) g_flag[cta] = 0;
    grid_barrier();   // only grid-wide sync in the whole kernel

    // ---- B ldmatrix lane geometry ----
    const int lr  = lid & 7;
    const int grp = lid >> 3;
    const uint32_t boff = (uint32_t)(((grp >> 1) * 8 + lr) * U_RSTRIDE + (grp & 1) * 16);
    const uint32_t uhib = sbase + OFF_UHI;
    const uint32_t ulob = sbase + OFF_ULO;

    const int rq = lid >> 2;
    const int jp = (lid & 3) * 2;
    const int kh2 = 2 * kh;

    float c_reg[4];
#pragma unroll
    for (int q = 0; q < 4; ++q) c_reg[q] = 0.0f;

    const size_t OFF_HL = (size_t)B * T * H;
    const size_t OFF_CL = OFF_HL + (size_t)B * H;

    int rb = 0;                       // t % 3
    for (int t = 0; t < T; ++t) {
        const int wbuf = (rb == 2) ? 0 : rb + 1;
        const uint4* HH = g_hfH[rb];
        const uint4* HL = g_hfL[rb];
        const int tgt = 64 * t;       // writes of steps 0..t-1 complete

        float4* zx4 = (float4*)(smem + OFF_ZX + (uint32_t)(t & 1) * 16384u);

        // acc: S1 = Ah*Bh, S2 = Ah*Bl + Al*Bh  [n][4]
        float S1[4][4], S2[4][4];
#pragma unroll
        for (int n = 0; n < 4; ++n)
#pragma unroll
            for (int r = 0; r < 4; ++r) { S1[n][r] = 0.f; S2[n][r] = 0.f; }

        // register double-buffer of A fragments; flags gate each chunk
        uint4 rH[2][2], rL[2][2];
        wait_flag(&g_flag[0], tgt);
        ldfrags(rH[0], rL[0], HH, HL, 0, kh2, m, lid);
        wait_flag(&g_flag[1], tgt);

#pragma unroll 2
        for (int c = 0; c < NCHUNK; ++c) {
            const int cur = c & 1, nxt = cur ^ 1;
            if (c + 1 < NCHUNK)       // flag[c+1] already confirmed
                ldfrags(rH[nxt], rL[nxt], HH, HL, c + 1, kh2, m, lid);

#pragma unroll
            for (int q = 0; q < 2; ++q) {
                const int K = 4 * c + kh2 + q;     // global kstep
                uint32_t bh[8], bl[8];
                LDSM_X4(bh[0], bh[1], bh[2], bh[3], uhib + boff + (uint32_t)K * 32u);
                LDSM_X4(bh[4], bh[5], bh[6], bh[7], uhib + boff + 16u * U_RSTRIDE + (uint32_t)K * 32u);
                LDSM_X4(bl[0], bl[1], bl[2], bl[3], ulob + boff + (uint32_t)K * 32u);
                LDSM_X4(bl[4], bl[5], bl[6], bl[7], ulob + boff + 16u * U_RSTRIDE + (uint32_t)K * 32u);
                const uint4 AH = rH[cur][q];
                const uint4 AL = rL[cur][q];
#pragma unroll
                for (int n = 0; n < 4; ++n) {
                    MMA_BF16(S1[n], AH.x, AH.y, AH.z, AH.w, bh[2 * n], bh[2 * n + 1]);
                    MMA_BF16(S2[n], AH.x, AH.y, AH.z, AH.w, bl[2 * n], bl[2 * n + 1]);
                    MMA_BF16(S2[n], AL.x, AL.y, AL.z, AL.w, bh[2 * n], bh[2 * n + 1]);
                }
            }
            if (c + 2 < NCHUNK)       // hoisted flag check overlaps next MMAs
                wait_flag(&g_flag[c + 2], tgt);
        }

        // ---- reduce the two k-halves (parity-buffered exchange) ----
        if (kh == 1) {
#pragma unroll
            for (int n = 0; n < 4; ++n) {
                int zi = (m * 4 + n) * 32 + lid;
                zx4[zi] = make_float4(S1[n][0] + S2[n][0],
                                      S1[n][1] + S2[n][1],
                                      S1[n][2] + S2[n][2],
                                      S1[n][3] + S2[n][3]);
            }
        }
        __syncthreads();

        // ---- epilogue on kh==0 warps (one m-tile each); kh==1 runs ahead ----
        if (kh == 0) {
            float zt[4][4];
#pragma unroll
            for (int n = 0; n < 4; ++n) {
                int zi = (m * 4 + n) * 32 + lid;
                float4 zp = zx4[zi];
                zt[n][0] = S1[n][0] + S2[n][0] + zp.x;
                zt[n][1] = S1[n][1] + S2[n][1] + zp.y;
                zt[n][2] = S1[n][2] + S2[n][2] + zp.z;
                zt[n][3] = S1[n][3] + S2[n][3] + zp.w;
            }
            const int blo = 16 * m + rq;
            float4 sLo = __ldg((const float4*)seq + ((size_t)blo * T + t));
            float4 sHi = __ldg((const float4*)seq + ((size_t)(blo + 8) * T + t));

            float hv4[4];
#pragma unroll
            for (int k = 0; k < 4; ++k) {
                const int b  = blo + (k >> 1) * 8;
                const int jj = jp + (k & 1);
                const float4 sv = (k < 2) ? sLo : sHi;
                float z[4];
#pragma unroll
                for (int g = 0; g < 4; ++g) {
                    const int cc = g * 8 + jj;
                    z[g] = zt[g][k] + bsl[cc]
                         + sv.x * Wsl[cc] + sv.y * Wsl[32 + cc]
                         + sv.z * Wsl[64 + cc] + sv.w * Wsl[96 + cc];
                }
                float ig = 1.0f / (1.0f + __expf(-z[0]));
                float fg = 1.0f / (1.0f + __expf(-z[1]));
                float gg = fmaxf(z[2], 0.0f);
                float og = 1.0f / (1.0f + __expf(-z[3]));
                float cn = fg * c_reg[k] + ig * gg;
                c_reg[k] = cn;
                float hv = og * fmaxf(cn, 0.0f);
                hv4[k] = hv;
                out[((size_t)b * T + t) * H + j0 + jj] = hv;
                if (write_extras && t == T - 1) {
                    out[OFF_HL + (size_t)b * H + j0 + jj] = hv;
                    out[OFF_CL + (size_t)b * H + j0 + jj] = cn;
                }
            }
            // h-frag writeback (lane slot == lid; 8B half selected by codd)
            __nv_bfloat16 h0 = __float2bfloat16(hv4[0]);
            __nv_bfloat16 h1 = __float2bfloat16(hv4[1]);
            __nv_bfloat16 h2 = __float2bfloat16(hv4[2]);
            __nv_bfloat16 h3 = __float2bfloat16(hv4[3]);
            __nv_bfloat16 l0 = __float2bfloat16(hv4[0] - __bfloat162float(h0));
            __nv_bfloat16 l1 = __float2bfloat16(hv4[1] - __bfloat162float(h1));
            __nv_bfloat16 l2 = __float2bfloat16(hv4[2] - __bfloat162float(h2));
            __nv_bfloat16 l3 = __float2bfloat16(hv4[3] - __bfloat162float(h3));
            int gidx = mychunk * 1024 + (Kc & 3) * 256 + m * 32 + lid;
            ((uint2*)&g_hfH[wbuf][gidx])[codd] =
                make_uint2(packbf(h0, h1), packbf(h2, h3));
            ((uint2*)&g_hfL[wbuf][gidx])[codd] =
                make_uint2(packbf(l0, l1), packbf(l2, l3));

            // publish: release this warp's share of the chunk flag
            __threadfence();
            if (lid == 0) atomicAdd(&g_flag[mychunk], 1);
        }

        rb = wbuf;
    }
}

extern "C" void kernel_launch(void* const* d_in, const int* in_sizes, int n_in,
                              void* d_out, int out_size)
{
    const float* seq  = (const float*)d_in[0];   // [128,256,4]
    const float* W    = (const float*)d_in[1];   // [4,4096]
    const float* U    = (const float*)d_in[2];   // [1024,4096]
    const float* bias = (const float*)d_in[3];   // [4096]
    float* out = (float*)d_out;

    long long need = (long long)B * T * H + 2LL * B * H;
    int write_extras = ((long long)out_size >= need) ? 1 : 0;

    cudaFuncSetAttribute(lstm_frag_kernel,
                         cudaFuncAttributeMaxDynamicSharedMemorySize, SMEM_TOTAL);
    lstm_frag_kernel<<<CTAS, THREADS, SMEM_TOTAL>>>(seq, W, U, bias, out,
                                                    write_extras);
}

// round 9
// speedup vs baseline: 1.5334x; 1.5334x over previous
#include <cuda_runtime.h>
#include <cuda_fp16.h>
#include <cstdint>

#define B       128
#define T       256
#define H       1024
#define NG      4096
#define THREADS 512
#define CTAS    128
#define JPC     8
#define NCHUNK  16          // 16 chunks of k=64
#define INV2048 (1.0f / 2048.0f)

// ---- persistent device state ----
// h (fp16) in mma-A-fragment layout: [buf][chunk*1024 + qs*256 + m*32 + lane]
__device__ uint4 g_hf[2][NCHUNK * 1024];
__device__ unsigned int g_bar_arrive = 0;
__device__ volatile unsigned int g_bar_gen = 0;

// ---- SMEM layout (bytes) ----
#define U_RSTRIDE 2064      // U^T rows padded -> conflict-free ldmatrix
#define OFF_UHI 0           // 66048
#define OFF_ULO 66048       // 66048 (U residual x2048, fp16)
#define OFF_ZX  132096      // 16384  z partial exchange (two-way kh split)
#define OFF_W   148480      // 4*32 f32
#define OFF_BS  148992      // 32 f32
#define SMEM_TOTAL 149120

__device__ __forceinline__ uint32_t smem_u32(const void* p) {
    uint32_t a;
    asm("{ .reg .u64 t; cvta.to.shared.u64 t, %1; cvt.u32.u64 %0, t; }"
        : "=r"(a) : "l"(p));
    return a;
}

#define LDSM_X4(r0, r1, r2, r3, a) \
    asm volatile("ldmatrix.sync.aligned.m8n8.x4.shared.b16 {%0,%1,%2,%3}, [%4];" \
                 : "=r"(r0), "=r"(r1), "=r"(r2), "=r"(r3) : "r"(a))

#define MMA_F16(d, a0, a1, a2, a3, b0, b1) \
    asm volatile("mma.sync.aligned.m16n8k16.row.col.f32.f16.f16.f32 " \
                 "{%0,%1,%2,%3}, {%4,%5,%6,%7}, {%8,%9}, {%0,%1,%2,%3};" \
                 : "+f"((d)[0]), "+f"((d)[1]), "+f"((d)[2]), "+f"((d)[3]) \
                 : "r"(a0), "r"(a1), "r"(a2), "r"(a3), "r"(b0), "r"(b1))

__device__ __forceinline__ void grid_barrier() {
    __syncthreads();
    __threadfence();
    if (threadIdx.x == 0) {
        unsigned int gen = g_bar_gen;
        if (atomicAdd(&g_bar_arrive, 1u) == CTAS - 1) {
            g_bar_arrive = 0;
            __threadfence();
            g_bar_gen = gen + 1;
        } else {
            while (g_bar_gen == gen) { }
        }
    }
    __syncthreads();
}

__device__ __forceinline__ uint32_t packh(__half a, __half b) {
    return (uint32_t)__half_as_ushort(a) | ((uint32_t)__half_as_ushort(b) << 16);
}

// load this warp's 2 A-fragments (q=0,1) for chunk c from L2 into regs
__device__ __forceinline__ void ldfrags(uint4* r, const uint4* __restrict__ HF,
                                        int c, int kh2, int m, int lid) {
#pragma unroll
    for (int q = 0; q < 2; ++q)
        r[q] = __ldcg(HF + c * 1024 + (kh2 + q) * 256 + m * 32 + lid);
}

__global__ void __launch_bounds__(THREADS, 1)
lstm_f16_kernel(const float* __restrict__ seq,
                const float* __restrict__ W,
                const float* __restrict__ U,
                const float* __restrict__ bias,
                float* __restrict__ out,
                int write_extras)
{
    extern __shared__ __align__(1024) uint8_t smem[];
    const uint32_t sbase = smem_u32(smem);
    const int tid = threadIdx.x;
    const int wid = tid >> 5;
    const int lid = tid & 31;
    const int m   = wid & 7;          // m-tile 0..7 (16 batch rows each)
    const int kh  = wid >> 3;         // k-half of each chunk
    const int cta = blockIdx.x;
    const int j0  = cta * JPC;
    const int Kc  = cta >> 1;         // frag kstep this CTA's j-columns land in
    const int codd = cta & 1;
    const int mychunk = Kc >> 2;

    float*  Wsl = (float*)(smem + OFF_W);
    float*  bsl = (float*)(smem + OFF_BS);
    float2* zx2 = (float2*)(smem + OFF_ZX);

    // ---------------- prologue ----------------
    // U slice -> U^T fp16 hi + fp16 (lo x 2048) (row n = gate*8+jj, k contiguous)
    for (int idx = tid; idx < 32 * H; idx += THREADS) {
        int k = idx >> 5, n = idx & 31;
        int gcol = ((n >> 3) << 10) + j0 + (n & 7);
        float v = U[(size_t)k * NG + gcol];
        __half hi = __float2half_rn(v);
        __half lo = __float2half_rn((v - __half2float(hi)) * 2048.0f);
        *(__half*)(smem + OFF_UHI + n * U_RSTRIDE + k * 2) = hi;
        *(__half*)(smem + OFF_ULO + n * U_RSTRIDE + k * 2) = lo;
    }
    if (tid < 4 * 32) {
        int f = tid >> 5, cc = tid & 31;
        Wsl[tid] = W[f * NG + ((cc >> 3) << 10) + j0 + (cc & 7)];
    }
    if (tid < 32)
        bsl[tid] = bias[((tid >> 3) << 10) + j0 + (tid & 7)];
    // zero-init this CTA's h-frag region in buf 0 (its 8B half of each elem)
    if (tid < 256) {
        int mm = tid >> 5, lane = tid & 31;
        int gidx = mychunk * 1024 + (Kc & 3) * 256 + mm * 32 + lane;
        ((uint2*)&g_hf[0][gidx])[codd] = make_uint2(0u, 0u);
    }
    grid_barrier();

    // ---- B ldmatrix lane geometry ----
    const int lr  = lid & 7;
    const int grp = lid >> 3;
    const uint32_t boff = (uint32_t)(((grp >> 1) * 8 + lr) * U_RSTRIDE + (grp & 1) * 16);
    const uint32_t uhib = sbase + OFF_UHI;
    const uint32_t ulob = sbase + OFF_ULO;

    const int rq = lid >> 2;
    const int jp = (lid & 3) * 2;
    const int kh2 = 2 * kh;
    const int okh = 1 - kh;
    const int bq  = 16 * m + rq + 8 * kh;    // the batch row this warp's epilogue owns

    float c_reg[2];
    c_reg[0] = 0.0f; c_reg[1] = 0.0f;

    const size_t OFF_HL = (size_t)B * T * H;
    const size_t OFF_CL = OFF_HL + (size_t)B * H;

    for (int t = 0; t < T; ++t) {
        const int rb = t & 1, wbuf = rb ^ 1;
        const uint4* HF = g_hf[rb];

        // acc: S1 = Ah*Bh, S2 = Ah*(Blo*2048)  [n][4]
        float S1[4][4], S2[4][4];
#pragma unroll
        for (int n = 0; n < 4; ++n)
#pragma unroll
            for (int r = 0; r < 4; ++r) { S1[n][r] = 0.f; S2[n][r] = 0.f; }

        // 3-deep register prefetch of A fragments; no syncs in GEMM
        uint4 rA[3][2];
        ldfrags(rA[0], HF, 0, kh2, m, lid);
        ldfrags(rA[1], HF, 1, kh2, m, lid);

#pragma unroll
        for (int c = 0; c < NCHUNK; ++c) {
            const int cur = c % 3;
            if (c + 2 < NCHUNK)
                ldfrags(rA[(c + 2) % 3], HF, c + 2, kh2, m, lid);

#pragma unroll
            for (int q = 0; q < 2; ++q) {
                const int K = 4 * c + kh2 + q;     // global kstep
                uint32_t bh[8], bl[8];
                LDSM_X4(bh[0], bh[1], bh[2], bh[3], uhib + boff + (uint32_t)K * 32u);
                LDSM_X4(bh[4], bh[5], bh[6], bh[7], uhib + boff + 16u * U_RSTRIDE + (uint32_t)K * 32u);
                LDSM_X4(bl[0], bl[1], bl[2], bl[3], ulob + boff + (uint32_t)K * 32u);
                LDSM_X4(bl[4], bl[5], bl[6], bl[7], ulob + boff + 16u * U_RSTRIDE + (uint32_t)K * 32u);
                const uint4 A = rA[cur][q];
#pragma unroll
                for (int n = 0; n < 4; ++n) {
                    MMA_F16(S1[n], A.x, A.y, A.z, A.w, bh[2 * n], bh[2 * n + 1]);
                    MMA_F16(S2[n], A.x, A.y, A.z, A.w, bl[2 * n], bl[2 * n + 1]);
                }
            }
        }

        // ---- two-way kh exchange of z partials ----
        // own cells: k = 2*kh,2*kh+1 ; partner cells: k = 2*okh,2*okh+1
#pragma unroll
        for (int n = 0; n < 4; ++n) {
            zx2[((kh * 8 + m) * 4 + n) * 32 + lid] =
                make_float2(S1[n][2 * okh]     + S2[n][2 * okh]     * INV2048,
                            S1[n][2 * okh + 1] + S2[n][2 * okh + 1] * INV2048);
        }
        __syncthreads();

        // ---- epilogue: all 16 warps, 1 batch row x 2 cells each ----
        {
            float zt[4][2];
#pragma unroll
            for (int n = 0; n < 4; ++n) {
                float2 p = zx2[((okh * 8 + m) * 4 + n) * 32 + lid];
                zt[n][0] = S1[n][2 * kh]     + S2[n][2 * kh]     * INV2048 + p.x;
                zt[n][1] = S1[n][2 * kh + 1] + S2[n][2 * kh + 1] * INV2048 + p.y;
            }
            const float4 sv = __ldg((const float4*)seq + ((size_t)bq * T + t));

            float hv2[2];
#pragma unroll
            for (int e = 0; e < 2; ++e) {
                const int jj = jp + e;
                float z[4];
#pragma unroll
                for (int g = 0; g < 4; ++g) {
                    const int cc = g * 8 + jj;
                    z[g] = zt[g][e] + bsl[cc]
                         + sv.x * Wsl[cc] + sv.y * Wsl[32 + cc]
                         + sv.z * Wsl[64 + cc] + sv.w * Wsl[96 + cc];
                }
                float ig = 1.0f / (1.0f + __expf(-z[0]));
                float fg = 1.0f / (1.0f + __expf(-z[1]));
                float gg = fmaxf(z[2], 0.0f);
                float og = 1.0f / (1.0f + __expf(-z[3]));
                float cn = fg * c_reg[e] + ig * gg;
                c_reg[e] = cn;
                float hv = og * fmaxf(cn, 0.0f);
                hv2[e] = hv;
                out[((size_t)bq * T + t) * H + j0 + jj] = hv;
                if (write_extras && t == T - 1) {
                    out[OFF_HL + (size_t)bq * H + j0 + jj] = hv;
                    out[OFF_CL + (size_t)bq * H + j0 + jj] = cn;
                }
            }
            // h-frag writeback: one 32-bit word (a-reg) per warp
            // word index: codd selects k-column byte-pair, kh selects row(+8)
            int gidx = mychunk * 1024 + (Kc & 3) * 256 + m * 32 + lid;
            ((uint32_t*)&g_hf[wbuf][gidx])[codd * 2 + kh] =
                packh(__float2half_rn(hv2[0]), __float2half_rn(hv2[1]));
        }
        grid_barrier();   // h complete chip-wide before next step's loads
    }
}

extern "C" void kernel_launch(void* const* d_in, const int* in_sizes, int n_in,
                              void* d_out, int out_size)
{
    const float* seq  = (const float*)d_in[0];   // [128,256,4]
    const float* W    = (const float*)d_in[1];   // [4,4096]
    const float* U    = (const float*)d_in[2];   // [1024,4096]
    const float* bias = (const float*)d_in[3];   // [4096]
    float* out = (float*)d_out;

    long long need = (long long)B * T * H + 2LL * B * H;
    int write_extras = ((long long)out_size >= need) ? 1 : 0;

    cudaFuncSetAttribute(lstm_f16_kernel,
                         cudaFuncAttributeMaxDynamicSharedMemorySize, SMEM_TOTAL);
    lstm_f16_kernel<<<CTAS, THREADS, SMEM_TOTAL>>>(seq, W, U, bias, out,
                                                   write_extras);
}

// round 10
// speedup vs baseline: 2.2881x; 1.4922x over previous
#include <cuda_runtime.h>
#include <cuda_fp16.h>
#include <cstdint>

#define B       128
#define T       256
#define H       1024
#define NG      4096
#define THREADS 512
#define CTAS    128
#define JPC     8
#define NK      32          // k16-steps per warp (k-half of 1024)

// ---- persistent device state ----
// h (fp16) in mma-A-fragment layout: [buf][K*256 + m*32 + lane] (uint4)
__device__ uint4 g_hf[2][64 * 256];
__device__ unsigned int g_bar_arrive = 0;
__device__ volatile unsigned int g_bar_gen = 0;

// ---- SMEM layout (bytes) ----
#define U_RSTRIDE 2064      // U^T rows padded -> conflict-free ldmatrix
#define OFF_UHI 0           // 66048 (single fp16)
#define OFF_ZX  66048       // 16384  z partial exchange (two-way kh split)
#define OFF_W   82432       // 4*32 f32
#define OFF_BS  82944       // 32 f32
#define SMEM_TOTAL 83072

__device__ __forceinline__ uint32_t smem_u32(const void* p) {
    uint32_t a;
    asm("{ .reg .u64 t; cvta.to.shared.u64 t, %1; cvt.u32.u64 %0, t; }"
        : "=r"(a) : "l"(p));
    return a;
}

#define LDSM_X4(r0, r1, r2, r3, a) \
    asm volatile("ldmatrix.sync.aligned.m8n8.x4.shared.b16 {%0,%1,%2,%3}, [%4];" \
                 : "=r"(r0), "=r"(r1), "=r"(r2), "=r"(r3) : "r"(a))

#define MMA_F16(d, a0, a1, a2, a3, b0, b1) \
    asm volatile("mma.sync.aligned.m16n8k16.row.col.f32.f16.f16.f32 " \
                 "{%0,%1,%2,%3}, {%4,%5,%6,%7}, {%8,%9}, {%0,%1,%2,%3};" \
                 : "+f"((d)[0]), "+f"((d)[1]), "+f"((d)[2]), "+f"((d)[3]) \
                 : "r"(a0), "r"(a1), "r"(a2), "r"(a3), "r"(b0), "r"(b1))

__device__ __forceinline__ void grid_barrier() {
    __syncthreads();
    __threadfence();
    if (threadIdx.x == 0) {
        unsigned int gen = g_bar_gen;
        if (atomicAdd(&g_bar_arrive, 1u) == CTAS - 1) {
            g_bar_arrive = 0;
            __threadfence();
            g_bar_gen = gen + 1;
        } else {
            while (g_bar_gen == gen) { }
        }
    }
    __syncthreads();
}

__device__ __forceinline__ uint32_t packh(__half a, __half b) {
    return (uint32_t)__half_as_ushort(a) | ((uint32_t)__half_as_ushort(b) << 16);
}

// warp's ks-th k16-step (ks 0..31) -> global kstep K
__device__ __forceinline__ int Kof(int ks, int kh2) {
    return 4 * (ks >> 1) + kh2 + (ks & 1);
}

__global__ void __launch_bounds__(THREADS, 1)
lstm_f16_kernel(const float* __restrict__ seq,
                const float* __restrict__ W,
                const float* __restrict__ U,
                const float* __restrict__ bias,
                float* __restrict__ out,
                int write_extras)
{
    extern __shared__ __align__(1024) uint8_t smem[];
    const uint32_t sbase = smem_u32(smem);
    const int tid = threadIdx.x;
    const int wid = tid >> 5;
    const int lid = tid & 31;
    const int m   = wid & 7;          // m-tile 0..7 (16 batch rows each)
    const int kh  = wid >> 3;         // k-half
    const int cta = blockIdx.x;
    const int j0  = cta * JPC;
    const int Kc  = cta >> 1;         // frag kstep this CTA's j-columns land in
    const int codd = cta & 1;

    float*  Wsl = (float*)(smem + OFF_W);
    float*  bsl = (float*)(smem + OFF_BS);
    float2* zx2 = (float2*)(smem + OFF_ZX);

    // ---------------- prologue ----------------
    // U slice -> U^T fp16 (row n = gate*8+jj, k contiguous)
    for (int idx = tid; idx < 32 * H; idx += THREADS) {
        int k = idx >> 5, n = idx & 31;
        int gcol = ((n >> 3) << 10) + j0 + (n & 7);
        *(__half*)(smem + OFF_UHI + n * U_RSTRIDE + k * 2) =
            __float2half_rn(U[(size_t)k * NG + gcol]);
    }
    if (tid < 4 * 32) {
        int f = tid >> 5, cc = tid & 31;
        Wsl[tid] = W[f * NG + ((cc >> 3) << 10) + j0 + (cc & 7)];
    }
    if (tid < 32)
        bsl[tid] = bias[((tid >> 3) << 10) + j0 + (tid & 7)];
    // zero-init this CTA's h-frag region in buf 0 (its 8B half of each elem)
    if (tid < 256) {
        int mm = tid >> 5, lane = tid & 31;
        ((uint2*)&g_hf[0][Kc * 256 + mm * 32 + lane])[codd] = make_uint2(0u, 0u);
    }
    grid_barrier();

    // ---- B ldmatrix lane geometry ----
    const int lr  = lid & 7;
    const int grp = lid >> 3;
    const uint32_t boff = (uint32_t)(((grp >> 1) * 8 + lr) * U_RSTRIDE + (grp & 1) * 16);
    const uint32_t uhib = sbase + OFF_UHI;

    const int rq = lid >> 2;
    const int jp = (lid & 3) * 2;
    const int kh2 = 2 * kh;
    const int okh = 1 - kh;
    const int bq  = 16 * m + rq + 8 * kh;    // batch row this warp's epilogue owns
    const int abase = m * 32 + lid;

    float c_reg[2];
    c_reg[0] = 0.0f; c_reg[1] = 0.0f;

    const size_t OFF_HL = (size_t)B * T * H;
    const size_t OFF_CL = OFF_HL + (size_t)B * H;

    for (int t = 0; t < T; ++t) {
        const int rb = t & 1, wbuf = rb ^ 1;
        const uint4* HF = g_hf[rb];

        float S1[4][4];
#pragma unroll
        for (int n = 0; n < 4; ++n)
#pragma unroll
            for (int r = 0; r < 4; ++r) S1[n][r] = 0.f;

        // pipelines: A 3-deep LDG prefetch, B 2-deep LDSM prefetch
        uint4 rA[3];
        uint32_t bb[2][8];
        rA[0] = __ldcg(HF + Kof(0, kh2) * 256 + abase);
        rA[1] = __ldcg(HF + Kof(1, kh2) * 256 + abase);
        {
            const uint32_t Kb = (uint32_t)Kof(0, kh2) * 32u;
            LDSM_X4(bb[0][0], bb[0][1], bb[0][2], bb[0][3], uhib + boff + Kb);
            LDSM_X4(bb[0][4], bb[0][5], bb[0][6], bb[0][7],
                    uhib + boff + 16u * U_RSTRIDE + Kb);
        }

#pragma unroll
        for (int ks = 0; ks < NK; ++ks) {
            const int cur = ks % 3, bcur = ks & 1;
            if (ks + 2 < NK)
                rA[(ks + 2) % 3] = __ldcg(HF + Kof(ks + 2, kh2) * 256 + abase);
            if (ks + 1 < NK) {
                const int bn = bcur ^ 1;
                const uint32_t Kb = (uint32_t)Kof(ks + 1, kh2) * 32u;
                LDSM_X4(bb[bn][0], bb[bn][1], bb[bn][2], bb[bn][3],
                        uhib + boff + Kb);
                LDSM_X4(bb[bn][4], bb[bn][5], bb[bn][6], bb[bn][7],
                        uhib + boff + 16u * U_RSTRIDE + Kb);
            }
            const uint4 A = rA[cur];
#pragma unroll
            for (int n = 0; n < 4; ++n)
                MMA_F16(S1[n], A.x, A.y, A.z, A.w, bb[bcur][2 * n], bb[bcur][2 * n + 1]);
        }

        // ---- two-way kh exchange of z partials ----
#pragma unroll
        for (int n = 0; n < 4; ++n) {
            zx2[((kh * 8 + m) * 4 + n) * 32 + lid] =
                make_float2(S1[n][2 * okh], S1[n][2 * okh + 1]);
        }
        __syncthreads();

        // ---- epilogue: all 16 warps, 1 batch row x 2 cells each ----
        {
            float zt[4][2];
#pragma unroll
            for (int n = 0; n < 4; ++n) {
                float2 p = zx2[((okh * 8 + m) * 4 + n) * 32 + lid];
                zt[n][0] = S1[n][2 * kh]     + p.x;
                zt[n][1] = S1[n][2 * kh + 1] + p.y;
            }
            const float4 sv = __ldg((const float4*)seq + ((size_t)bq * T + t));

            float hv2[2];
#pragma unroll
            for (int e = 0; e < 2; ++e) {
                const int jj = jp + e;
                float z[4];
#pragma unroll
                for (int g = 0; g < 4; ++g) {
                    const int cc = g * 8 + jj;
                    z[g] = zt[g][e] + bsl[cc]
                         + sv.x * Wsl[cc] + sv.y * Wsl[32 + cc]
                         + sv.z * Wsl[64 + cc] + sv.w * Wsl[96 + cc];
                }
                float ig = 1.0f / (1.0f + __expf(-z[0]));
                float fg = 1.0f / (1.0f + __expf(-z[1]));
                float gg = fmaxf(z[2], 0.0f);
                float og = 1.0f / (1.0f + __expf(-z[3]));
                float cn = fg * c_reg[e] + ig * gg;
                c_reg[e] = cn;
                float hv = og * fmaxf(cn, 0.0f);
                hv2[e] = hv;
                out[((size_t)bq * T + t) * H + j0 + jj] = hv;
                if (write_extras && t == T - 1) {
                    out[OFF_HL + (size_t)bq * H + j0 + jj] = hv;
                    out[OFF_CL + (size_t)bq * H + j0 + jj] = cn;
                }
            }
            // h-frag writeback: one 32-bit word per warp
            ((uint32_t*)&g_hf[wbuf][Kc * 256 + m * 32 + lid])[codd * 2 + kh] =
                packh(__float2half_rn(hv2[0]), __float2half_rn(hv2[1]));
        }
        grid_barrier();   // h complete chip-wide before next step's loads
    }
}

extern "C" void kernel_launch(void* const* d_in, const int* in_sizes, int n_in,
                              void* d_out, int out_size)
{
    const float* seq  = (const float*)d_in[0];   // [128,256,4]
    const float* W    = (const float*)d_in[1];   // [4,4096]
    const float* U    = (const float*)d_in[2];   // [1024,4096]
    const float* bias = (const float*)d_in[3];   // [4096]
    float* out = (float*)d_out;

    long long need = (long long)B * T * H + 2LL * B * H;
    int write_extras = ((long long)out_size >= need) ? 1 : 0;

    cudaFuncSetAttribute(lstm_f16_kernel,
                         cudaFuncAttributeMaxDynamicSharedMemorySize, SMEM_TOTAL);
    lstm_f16_kernel<<<CTAS, THREADS, SMEM_TOTAL>>>(seq, W, U, bias, out,
                                                   write_extras);
}

// round 11
// speedup vs baseline: 2.2971x; 1.0039x over previous
#include <cuda_runtime.h>
#include <cuda_fp16.h>
#include <cstdint>

#define B       128
#define T       256
#define H       1024
#define NG      4096
#define THREADS 512
#define CTAS    128
#define JPC     8
#define NKQ     16          // k16-steps per warp (k-quarter of 1024)

// ---- persistent device state ----
// h (fp16) in mma-A-fragment layout: [buf][K*256 + m*32 + lane] (uint4)
__device__ uint4 g_hf[2][64 * 256];
__device__ unsigned int g_bar_arrive = 0;
__device__ volatile unsigned int g_bar_gen = 0;

// ---- SMEM layout (bytes) ----
#define U_RSTRIDE 2064      // U^T rows padded -> conflict-free ldmatrix
#define OFF_UHI 0           // 66048 (single fp16)
#define OFF_ZX  66048       // 65536  z partial exchange (4-way kq reduction)
#define OFF_W   131584      // 4*32 f32
#define OFF_BS  132096      // 32 f32
#define SMEM_TOTAL 132224

__device__ __forceinline__ uint32_t smem_u32(const void* p) {
    uint32_t a;
    asm("{ .reg .u64 t; cvta.to.shared.u64 t, %1; cvt.u32.u64 %0, t; }"
        : "=r"(a) : "l"(p));
    return a;
}

#define LDSM_X4(r0, r1, r2, r3, a) \
    asm volatile("ldmatrix.sync.aligned.m8n8.x4.shared.b16 {%0,%1,%2,%3}, [%4];" \
                 : "=r"(r0), "=r"(r1), "=r"(r2), "=r"(r3) : "r"(a))

#define MMA_F16(d, a0, a1, a2, a3, b0, b1) \
    asm volatile("mma.sync.aligned.m16n8k16.row.col.f32.f16.f16.f32 " \
                 "{%0,%1,%2,%3}, {%4,%5,%6,%7}, {%8,%9}, {%0,%1,%2,%3};" \
                 : "+f"((d)[0]), "+f"((d)[1]), "+f"((d)[2]), "+f"((d)[3]) \
                 : "r"(a0), "r"(a1), "r"(a2), "r"(a3), "r"(b0), "r"(b1))

__device__ __forceinline__ void grid_barrier() {
    __syncthreads();
    __threadfence();
    if (threadIdx.x == 0) {
        unsigned int gen = g_bar_gen;
        if (atomicAdd(&g_bar_arrive, 1u) == CTAS - 1) {
            g_bar_arrive = 0;
            __threadfence();
            g_bar_gen = gen + 1;
        } else {
            while (g_bar_gen == gen) { }
        }
    }
    __syncthreads();
}

__device__ __forceinline__ uint32_t packh(__half a, __half b) {
    return (uint32_t)__half_as_ushort(a) | ((uint32_t)__half_as_ushort(b) << 16);
}

__global__ void __launch_bounds__(THREADS, 1)
lstm_f16_kernel(const float* __restrict__ seq,
                const float* __restrict__ W,
                const float* __restrict__ U,
                const float* __restrict__ bias,
                float* __restrict__ out,
                int write_extras)
{
    extern __shared__ __align__(1024) uint8_t smem[];
    const uint32_t sbase = smem_u32(smem);
    const int tid = threadIdx.x;
    const int wid = tid >> 5;
    const int lid = tid & 31;
    const int mg  = wid & 3;          // m-group: m-tiles 2mg, 2mg+1
    const int kq  = wid >> 2;         // k-quarter 0..3
    const int cta = blockIdx.x;
    const int j0  = cta * JPC;
    const int Kc  = cta >> 1;         // frag kstep this CTA's j-columns land in
    const int codd = cta & 1;

    float*  Wsl = (float*)(smem + OFF_W);
    float*  bsl = (float*)(smem + OFF_BS);
    float4* zx4 = (float4*)(smem + OFF_ZX);
    const float2* zx2 = (const float2*)(smem + OFF_ZX);

    // ---------------- prologue ----------------
    // U slice -> U^T fp16 (row n = gate*8+jj, k contiguous)
    for (int idx = tid; idx < 32 * H; idx += THREADS) {
        int k = idx >> 5, n = idx & 31;
        int gcol = ((n >> 3) << 10) + j0 + (n & 7);
        *(__half*)(smem + OFF_UHI + n * U_RSTRIDE + k * 2) =
            __float2half_rn(U[(size_t)k * NG + gcol]);
    }
    if (tid < 4 * 32) {
        int f = tid >> 5, cc = tid & 31;
        Wsl[tid] = W[f * NG + ((cc >> 3) << 10) + j0 + (cc & 7)];
    }
    if (tid < 32)
        bsl[tid] = bias[((tid >> 3) << 10) + j0 + (tid & 7)];
    // zero-init this CTA's h-frag region in buf 0 (its 8B half of each elem)
    if (tid < 256) {
        int mm = tid >> 5, lane = tid & 31;
        ((uint2*)&g_hf[0][Kc * 256 + mm * 32 + lane])[codd] = make_uint2(0u, 0u);
    }
    grid_barrier();

    // ---- B ldmatrix lane geometry ----
    const int lr  = lid & 7;
    const int grp = lid >> 3;
    const uint32_t boff = (uint32_t)(((grp >> 1) * 8 + lr) * U_RSTRIDE + (grp & 1) * 16);
    const uint32_t uhib = sbase + OFF_UHI;

    const int rq = lid >> 2;
    const int jp = (lid & 3) * 2;
    const int m0 = 2 * mg;            // first of this warp's two m-tiles
    const int Kbase = 16 * kq;

    // epilogue ownership: octet o covers rows 8o..8o+7
    const int o    = 4 * mg + kq;
    const int mt_o = o >> 1;          // owned m-tile (== m0 + (kq>>1))
    const int half = o & 1;           // row half within the m16 tile
    const int mtl_o = kq >> 1;        // local index of owned m-tile
    const int bq   = 8 * o + rq;      // owned batch row

    float c_reg[2];
    c_reg[0] = 0.0f; c_reg[1] = 0.0f;

    const size_t OFF_HL = (size_t)B * T * H;
    const size_t OFF_CL = OFF_HL + (size_t)B * H;

    for (int t = 0; t < T; ++t) {
        const int rb = t & 1, wbuf = rb ^ 1;
        const uint4* HF = g_hf[rb];

        float S1[2][4][4];
#pragma unroll
        for (int mtl = 0; mtl < 2; ++mtl)
#pragma unroll
            for (int n = 0; n < 4; ++n)
#pragma unroll
                for (int r = 0; r < 4; ++r) S1[mtl][n][r] = 0.f;

        // A: 2-deep register prefetch (2 m-tiles per slot); B: single buffer
        uint4 rA[2][2];
#pragma unroll
        for (int mtl = 0; mtl < 2; ++mtl)
            rA[0][mtl] = __ldcg(HF + Kbase * 256 + (m0 + mtl) * 32 + lid);

#pragma unroll
        for (int ks = 0; ks < NKQ; ++ks) {
            const int cur = ks & 1, nxt = cur ^ 1;
            if (ks + 1 < NKQ) {
#pragma unroll
                for (int mtl = 0; mtl < 2; ++mtl)
                    rA[nxt][mtl] = __ldcg(HF + (Kbase + ks + 1) * 256
                                             + (m0 + mtl) * 32 + lid);
            }
            const uint32_t Kb = (uint32_t)(Kbase + ks) * 32u;
            uint32_t bh[8];
            LDSM_X4(bh[0], bh[1], bh[2], bh[3], uhib + boff + Kb);
            LDSM_X4(bh[4], bh[5], bh[6], bh[7],
                    uhib + boff + 16u * U_RSTRIDE + Kb);
#pragma unroll
            for (int mtl = 0; mtl < 2; ++mtl) {
                const uint4 A = rA[cur][mtl];
#pragma unroll
                for (int n = 0; n < 4; ++n)
                    MMA_F16(S1[mtl][n], A.x, A.y, A.z, A.w,
                            bh[2 * n], bh[2 * n + 1]);
            }
        }

        // ---- 4-way kq reduction: publish all partials ----
#pragma unroll
        for (int mtl = 0; mtl < 2; ++mtl) {
            const int mt = m0 + mtl;
#pragma unroll
            for (int n = 0; n < 4; ++n)
                zx4[((kq * 8 + mt) * 4 + n) * 32 + lid] =
                    make_float4(S1[mtl][n][0], S1[mtl][n][1],
                                S1[mtl][n][2], S1[mtl][n][3]);
        }
        __syncthreads();

        // ---- epilogue: all 16 warps, 1 row-octet x 2 cells each ----
        {
            float zt[4][2];
#pragma unroll
            for (int n = 0; n < 4; ++n) {
                zt[n][0] = S1[mtl_o][n][2 * half];
                zt[n][1] = S1[mtl_o][n][2 * half + 1];
#pragma unroll
                for (int qq = 0; qq < 4; ++qq) {
                    if (qq == kq) continue;
                    float2 p = zx2[(((qq * 8 + mt_o) * 4 + n) * 32 + lid) * 2 + half];
                    zt[n][0] += p.x;
                    zt[n][1] += p.y;
                }
            }
            const float4 sv = __ldg((const float4*)seq + ((size_t)bq * T + t));

            float hv2[2];
#pragma unroll
            for (int e = 0; e < 2; ++e) {
                const int jj = jp + e;
                float z[4];
#pragma unroll
                for (int g = 0; g < 4; ++g) {
                    const int cc = g * 8 + jj;
                    z[g] = zt[g][e] + bsl[cc]
                         + sv.x * Wsl[cc] + sv.y * Wsl[32 + cc]
                         + sv.z * Wsl[64 + cc] + sv.w * Wsl[96 + cc];
                }
                float ig = 1.0f / (1.0f + __expf(-z[0]));
                float fg = 1.0f / (1.0f + __expf(-z[1]));
                float gg = fmaxf(z[2], 0.0f);
                float og = 1.0f / (1.0f + __expf(-z[3]));
                float cn = fg * c_reg[e] + ig * gg;
                c_reg[e] = cn;
                float hv = og * fmaxf(cn, 0.0f);
                hv2[e] = hv;
                out[((size_t)bq * T + t) * H + j0 + jj] = hv;
                if (write_extras && t == T - 1) {
                    out[OFF_HL + (size_t)bq * H + j0 + jj] = hv;
                    out[OFF_CL + (size_t)bq * H + j0 + jj] = cn;
                }
            }
            // h-frag writeback: one 32-bit word per warp
            ((uint32_t*)&g_hf[wbuf][Kc * 256 + mt_o * 32 + lid])[codd * 2 + half] =
                packh(__float2half_rn(hv2[0]), __float2half_rn(hv2[1]));
        }
        grid_barrier();   // h complete chip-wide before next step's loads
    }
}

extern "C" void kernel_launch(void* const* d_in, const int* in_sizes, int n_in,
                              void* d_out, int out_size)
{
    const float* seq  = (const float*)d_in[0];   // [128,256,4]
    const float* W    = (const float*)d_in[1];   // [4,4096]
    const float* U    = (const float*)d_in[2];   // [1024,4096]
    const float* bias = (const float*)d_in[3];   // [4096]
    float* out = (float*)d_out;

    long long need = (long long)B * T * H + 2LL * B * H;
    int write_extras = ((long long)out_size >= need) ? 1 : 0;

    cudaFuncSetAttribute(lstm_f16_kernel,
                         cudaFuncAttributeMaxDynamicSharedMemorySize, SMEM_TOTAL);
    lstm_f16_kernel<<<CTAS, THREADS, SMEM_TOTAL>>>(seq, W, U, bias, out,
                                                   write_extras);
}